// round 2
// baseline (speedup 1.0000x reference)
#include <cuda_runtime.h>
#include <math.h>

#define NMAX 100000

// Static scratch: ~52 MB total (kept small to stay under the harness's
// module-load allocation tolerance).
__device__ float g_y[(size_t)NMAX * 128];  // persistent feature buffer (stride 128)
__device__ float g_dinv[NMAX];
__device__ int   g_deg[NMAX];

// ---------------- degree / norm ----------------
__global__ void k_deg_init(int n) {
    int i = blockIdx.x * blockDim.x + threadIdx.x;
    if (i < n) g_deg[i] = 1;  // self loop included
}

__global__ void k_deg_count(const int* __restrict__ dst, int E) {
    int e = blockIdx.x * blockDim.x + threadIdx.x;
    if (e < E) atomicAdd(&g_deg[dst[e]], 1);
}

__global__ void k_dinv(int n) {
    int i = blockIdx.x * blockDim.x + threadIdx.x;
    if (i < n) g_dinv[i] = rsqrtf((float)g_deg[i]);
}

// ---------------- GEMM (COUT=64) + self-loop seed ----------------
// h[r, 0:64] = x[r, :] @ W[:, wcoff:wcoff+64]
// agg[r]     = h[r] * dinv[r]^2            (self-loop term, seeds accumulator)
// In-place safe: each block stages its input rows to smem (sync) before writing.
template <int CIN>
__global__ void k_gemm64(const float* __restrict__ x, int xstride,
                         const float* __restrict__ W, int wstride, int wcoff,
                         float* __restrict__ h, int hstride,
                         float* __restrict__ agg, int aggstride, int n) {
    constexpr int TB = 256;
    constexpr int COUT = 64;
    constexpr int RP = TB / COUT;  // 4 rows in flight
    constexpr int ITER = 8;        // 32 rows per block
    __shared__ float Ws[CIN * COUT];
    __shared__ float xs[RP][CIN];

    for (int i = threadIdx.x; i < CIN * COUT; i += TB)
        Ws[i] = W[(i / COUT) * wstride + wcoff + (i % COUT)];

    const int c = threadIdx.x % COUT;
    const int rsub = threadIdx.x / COUT;
    const int row0 = blockIdx.x * (RP * ITER);

#pragma unroll
    for (int it = 0; it < ITER; ++it) {
        __syncthreads();  // prior iter compute done (covers Ws on it=0)
        for (int i = threadIdx.x; i < RP * CIN; i += TB) {
            int rr = row0 + it * RP + i / CIN;
            xs[i / CIN][i % CIN] = (rr < n) ? x[(size_t)rr * xstride + (i % CIN)] : 0.0f;
        }
        __syncthreads();
        int r = row0 + it * RP + rsub;
        if (r < n) {
            float acc = 0.0f;
#pragma unroll
            for (int k = 0; k < CIN; ++k)
                acc = fmaf(xs[rsub][k], Ws[k * COUT + c], acc);
            float dv = g_dinv[r];
            h[(size_t)r * hstride + c] = acc;
            agg[(size_t)r * aggstride + c] = acc * dv * dv;
        }
    }
}

// ---------------- edge scatter-add (64 channels) ----------------
// agg[dst] += h[src] * dinv[src] * dinv[dst]
__global__ void k_scatter64(const int* __restrict__ src, const int* __restrict__ dst,
                            int E, const float* __restrict__ h, int hstride,
                            float* __restrict__ agg, int aggstride) {
    constexpr int TPE = 16;  // 16 threads x float4 = 64 channels
    long long tid = (long long)blockIdx.x * blockDim.x + threadIdx.x;
    int e = (int)(tid / TPE);
    int lane = (int)(tid % TPE);
    if (e >= E) return;
    int s = __ldg(src + e);
    int d = __ldg(dst + e);
    float norm = g_dinv[s] * g_dinv[d];
    const float4 v = *reinterpret_cast<const float4*>(&h[(size_t)s * hstride + lane * 4]);
    float* o = &agg[(size_t)d * aggstride + lane * 4];
    atomicAdd(o + 0, v.x * norm);
    atomicAdd(o + 1, v.y * norm);
    atomicAdd(o + 2, v.z * norm);
    atomicAdd(o + 3, v.w * norm);
}

// ---------------- bias + (optional) relu, 64 channels ----------------
template <bool RELU>
__global__ void k_fin64(const float* __restrict__ b,
                        const float* __restrict__ agg, int aggstride,
                        float* __restrict__ y, int ystride, int n) {
    int idx = blockIdx.x * blockDim.x + threadIdx.x;
    int total4 = n * 16;
    if (idx >= total4) return;
    int row = idx >> 4;
    int c4 = idx & 15;
    float4 bb = *reinterpret_cast<const float4*>(b + c4 * 4);
    float4 v = *reinterpret_cast<const float4*>(&agg[(size_t)row * aggstride + c4 * 4]);
    v.x += bb.x; v.y += bb.y; v.z += bb.z; v.w += bb.w;
    if (RELU) {
        v.x = fmaxf(v.x, 0.0f); v.y = fmaxf(v.y, 0.0f);
        v.z = fmaxf(v.z, 0.0f); v.w = fmaxf(v.w, 0.0f);
    }
    *reinterpret_cast<float4*>(&y[(size_t)row * ystride + c4 * 4]) = v;
}

// ---------------- launch ----------------
extern "C" void kernel_launch(void* const* d_in, const int* in_sizes, int n_in,
                              void* d_out, int out_size) {
    const float* x  = (const float*)d_in[0];
    const int*   ei = (const int*)d_in[1];
    const float* W1 = (const float*)d_in[2];
    const float* b1 = (const float*)d_in[3];
    const float* W2 = (const float*)d_in[4];
    const float* b2 = (const float*)d_in[5];
    const float* W3 = (const float*)d_in[6];
    const float* b3 = (const float*)d_in[7];
    float* dout = (float*)d_out;  // N x 64 — doubles as the agg accumulator

    const int n = in_sizes[0] / 13;
    const int E = in_sizes[1] / 2;
    const int* src = ei;
    const int* dst = ei + E;

    const int TB = 256;
    auto cdiv = [](long long a, long long b) { return (int)((a + b - 1) / b); };
    const int g_gemm = cdiv(n, 32);
    const int g_scat = cdiv((long long)E * 16, TB);
    const int g_fin  = cdiv((long long)n * 16, TB);

    float* y = nullptr;
    cudaGetSymbolAddress((void**)&y, g_y);  // stride 128

    // normalization
    k_deg_init<<<cdiv(n, TB), TB>>>(n);
    k_deg_count<<<cdiv(E, TB), TB>>>(dst, E);
    k_dinv<<<cdiv(n, TB), TB>>>(n);

    // ---- layer 1 (13 -> 128), two 64-col passes; agg lives in d_out ----
    // pass A: cols 0..63
    k_gemm64<13><<<g_gemm, 256>>>(x, 13, W1, 128, 0, y, 128, dout, 64, n);
    k_scatter64<<<g_scat, TB>>>(src, dst, E, y, 128, dout, 64);
    k_fin64<true><<<g_fin, TB>>>(b1, dout, 64, y, 128, n);
    // pass B: cols 64..127
    k_gemm64<13><<<g_gemm, 256>>>(x, 13, W1, 128, 64, y + 64, 128, dout, 64, n);
    k_scatter64<<<g_scat, TB>>>(src, dst, E, y + 64, 128, dout, 64);
    k_fin64<true><<<g_fin, TB>>>(b1 + 64, dout, 64, y + 64, 128, n);

    // ---- layer 2 (128 -> 64): h2 in-place into y cols 0..63 ----
    k_gemm64<128><<<g_gemm, 256>>>(y, 128, W2, 64, 0, y, 128, dout, 64, n);
    k_scatter64<<<g_scat, TB>>>(src, dst, E, y, 128, dout, 64);
    k_fin64<true><<<g_fin, TB>>>(b2, dout, 64, y, 128, n);

    // ---- layer 3 (64 -> 64): h3 into y cols 64..127; result in d_out ----
    k_gemm64<64><<<g_gemm, 256>>>(y, 128, W3, 64, 0, y + 64, 128, dout, 64, n);
    k_scatter64<<<g_scat, TB>>>(src, dst, E, y + 64, 128, dout, 64);
    k_fin64<false><<<g_fin, TB>>>(b3, dout, 64, dout, 64, n);
}

// round 3
// speedup vs baseline: 2.3071x; 2.3071x over previous
#include <cuda_runtime.h>
#include <math.h>

#define NMAX   100000
#define EMAX   1600000
#define SCAN_B 512

// Static scratch ~60 MB.
__device__ float g_y[(size_t)NMAX * 128];   // persistent feature buffer (stride 128)
__device__ float g_dinv[NMAX];
__device__ int   g_deg[NMAX];     // edge-only in-degree
__device__ int   g_rowptr[NMAX];  // exclusive scan of g_deg
__device__ int   g_cursor[NMAX];
__device__ int   g_csr[EMAX];     // src ids grouped by dst
__device__ int   g_bsums[1024];

// ---------------- degree / norm / CSR ----------------
__global__ void k_zero(int n) {
    int i = blockIdx.x * blockDim.x + threadIdx.x;
    if (i < n) { g_deg[i] = 0; g_cursor[i] = 0; }
}

__global__ void k_deg_count(const int* __restrict__ dst, int E) {
    int e = blockIdx.x * blockDim.x + threadIdx.x;
    if (e < E) atomicAdd(&g_deg[dst[e]], 1);
}

__global__ void k_dinv(int n) {
    int i = blockIdx.x * blockDim.x + threadIdx.x;
    if (i < n) g_dinv[i] = rsqrtf((float)(g_deg[i] + 1));  // +1 self loop
}

// exclusive scan of g_deg -> g_rowptr (3-phase)
__global__ void k_scan1(int n) {
    __shared__ int sm[SCAN_B];
    int gid = blockIdx.x * SCAN_B + threadIdx.x;
    int v = (gid < n) ? g_deg[gid] : 0;
    sm[threadIdx.x] = v;
    __syncthreads();
    for (int off = 1; off < SCAN_B; off <<= 1) {
        int t = (threadIdx.x >= off) ? sm[threadIdx.x - off] : 0;
        __syncthreads();
        sm[threadIdx.x] += t;
        __syncthreads();
    }
    if (gid < n) g_rowptr[gid] = sm[threadIdx.x] - v;  // exclusive within block
    if (threadIdx.x == SCAN_B - 1) g_bsums[blockIdx.x] = sm[SCAN_B - 1];
}

__global__ void k_scan2(int nb) {  // single block, nb <= SCAN_B
    __shared__ int sm[SCAN_B];
    int v = (threadIdx.x < nb) ? g_bsums[threadIdx.x] : 0;
    sm[threadIdx.x] = v;
    __syncthreads();
    for (int off = 1; off < SCAN_B; off <<= 1) {
        int t = (threadIdx.x >= off) ? sm[threadIdx.x - off] : 0;
        __syncthreads();
        sm[threadIdx.x] += t;
        __syncthreads();
    }
    if (threadIdx.x < nb) g_bsums[threadIdx.x] = sm[threadIdx.x];  // inclusive
}

__global__ void k_scan3(int n) {
    int gid = blockIdx.x * SCAN_B + threadIdx.x;
    if (gid >= n || blockIdx.x == 0) return;
    g_rowptr[gid] += g_bsums[blockIdx.x - 1];
}

__global__ void k_place(const int* __restrict__ src, const int* __restrict__ dst, int E) {
    int e = blockIdx.x * blockDim.x + threadIdx.x;
    if (e >= E) return;
    int d = dst[e];
    int pos = g_rowptr[d] + atomicAdd(&g_cursor[d], 1);
    g_csr[pos] = src[e];
}

// ---------------- GEMM (COUT=64): hs = (x @ W[:, off:off+64]) * dinv ----------------
template <int CIN>
__global__ void k_gemm64(const float* __restrict__ x, int xstride,
                         const float* __restrict__ W, int wstride, int wcoff,
                         float* __restrict__ hs, int hstride, int n) {
    constexpr int TB = 256;
    constexpr int COUT = 64;
    constexpr int RP = TB / COUT;  // 4 rows in flight
    constexpr int ITER = 8;        // 32 rows per block
    __shared__ float Ws[CIN * COUT];
    __shared__ float xs[RP][CIN];

    for (int i = threadIdx.x; i < CIN * COUT; i += TB)
        Ws[i] = W[(i / COUT) * wstride + wcoff + (i % COUT)];

    const int c = threadIdx.x % COUT;
    const int rsub = threadIdx.x / COUT;
    const int row0 = blockIdx.x * (RP * ITER);

#pragma unroll
    for (int it = 0; it < ITER; ++it) {
        __syncthreads();
        for (int i = threadIdx.x; i < RP * CIN; i += TB) {
            int rr = row0 + it * RP + i / CIN;
            xs[i / CIN][i % CIN] = (rr < n) ? x[(size_t)rr * xstride + (i % CIN)] : 0.0f;
        }
        __syncthreads();
        int r = row0 + it * RP + rsub;
        if (r < n) {
            float acc = 0.0f;
#pragma unroll
            for (int k = 0; k < CIN; ++k)
                acc = fmaf(xs[rsub][k], Ws[k * COUT + c], acc);
            hs[(size_t)r * hstride + c] = acc * g_dinv[r];
        }
    }
}

// ---------------- CSR gather aggregation + bias (+relu) ----------------
// y[d] = dinv[d] * (hs[d] + sum_{s in N(d)} hs[s]) + b
// One warp per node; lane owns channels [2*lane, 2*lane+1].
template <bool RELU>
__global__ void k_agg(const float* __restrict__ hs, int hstride,
                      const float* __restrict__ b,
                      float* __restrict__ y, int ystride, int n) {
    int node = blockIdx.x * (blockDim.x >> 5) + (threadIdx.x >> 5);
    int lane = threadIdx.x & 31;
    if (node >= n) return;

    float2 acc = *reinterpret_cast<const float2*>(&hs[(size_t)node * hstride + lane * 2]);
    int start = g_rowptr[node];
    int end = start + g_deg[node];

    for (int j0 = start; j0 < end; j0 += 32) {
        int idx = 0;
        if (j0 + lane < end) idx = __ldg(&g_csr[j0 + lane]);
        int cnt = min(32, end - j0);
        int t = 0;
        for (; t + 4 <= cnt; t += 4) {
            int s0 = __shfl_sync(0xffffffffu, idx, t + 0);
            int s1 = __shfl_sync(0xffffffffu, idx, t + 1);
            int s2 = __shfl_sync(0xffffffffu, idx, t + 2);
            int s3 = __shfl_sync(0xffffffffu, idx, t + 3);
            float2 v0 = *reinterpret_cast<const float2*>(&hs[(size_t)s0 * hstride + lane * 2]);
            float2 v1 = *reinterpret_cast<const float2*>(&hs[(size_t)s1 * hstride + lane * 2]);
            float2 v2 = *reinterpret_cast<const float2*>(&hs[(size_t)s2 * hstride + lane * 2]);
            float2 v3 = *reinterpret_cast<const float2*>(&hs[(size_t)s3 * hstride + lane * 2]);
            acc.x += (v0.x + v1.x) + (v2.x + v3.x);
            acc.y += (v0.y + v1.y) + (v2.y + v3.y);
        }
        for (; t < cnt; ++t) {
            int s = __shfl_sync(0xffffffffu, idx, t);
            float2 v = *reinterpret_cast<const float2*>(&hs[(size_t)s * hstride + lane * 2]);
            acc.x += v.x;
            acc.y += v.y;
        }
    }

    float dv = g_dinv[node];
    float2 bb = *reinterpret_cast<const float2*>(&b[lane * 2]);
    float2 o;
    o.x = fmaf(acc.x, dv, bb.x);
    o.y = fmaf(acc.y, dv, bb.y);
    if (RELU) { o.x = fmaxf(o.x, 0.0f); o.y = fmaxf(o.y, 0.0f); }
    *reinterpret_cast<float2*>(&y[(size_t)node * ystride + lane * 2]) = o;
}

// ---------------- launch ----------------
extern "C" void kernel_launch(void* const* d_in, const int* in_sizes, int n_in,
                              void* d_out, int out_size) {
    const float* x  = (const float*)d_in[0];
    const int*   ei = (const int*)d_in[1];
    const float* W1 = (const float*)d_in[2];
    const float* b1 = (const float*)d_in[3];
    const float* W2 = (const float*)d_in[4];
    const float* b2 = (const float*)d_in[5];
    const float* W3 = (const float*)d_in[6];
    const float* b3 = (const float*)d_in[7];
    float* dout = (float*)d_out;  // N x 64 — reused as the hs buffer for layers 1,2

    const int n = in_sizes[0] / 13;
    const int E = in_sizes[1] / 2;
    const int* src = ei;
    const int* dst = ei + E;

    const int TB = 256;
    auto cdiv = [](long long a, long long b) { return (int)((a + b - 1) / b); };
    const int g_gemm = cdiv(n, 32);
    const int g_aggg = cdiv(n, TB / 32);
    const int nb = cdiv(n, SCAN_B);

    float* y = nullptr;
    cudaGetSymbolAddress((void**)&y, g_y);  // stride 128

    // ---- CSR build (once; shared by all layers) ----
    k_zero<<<cdiv(n, TB), TB>>>(n);
    k_deg_count<<<cdiv(E, TB), TB>>>(dst, E);
    k_dinv<<<cdiv(n, TB), TB>>>(n);
    k_scan1<<<nb, SCAN_B>>>(n);
    k_scan2<<<1, SCAN_B>>>(nb);
    k_scan3<<<nb, SCAN_B>>>(n);
    k_place<<<cdiv(E, TB), TB>>>(src, dst, E);

    // ---- layer 1 (13 -> 128), two 64-col passes; hs in d_out ----
    k_gemm64<13><<<g_gemm, TB>>>(x, 13, W1, 128, 0, dout, 64, n);
    k_agg<true><<<g_aggg, TB>>>(dout, 64, b1, y, 128, n);
    k_gemm64<13><<<g_gemm, TB>>>(x, 13, W1, 128, 64, dout, 64, n);
    k_agg<true><<<g_aggg, TB>>>(dout, 64, b1 + 64, y + 64, 128, n);

    // ---- layer 2 (128 -> 64): hs in d_out, y2 into g_y cols 0..63 ----
    k_gemm64<128><<<g_gemm, TB>>>(y, 128, W2, 64, 0, dout, 64, n);
    k_agg<true><<<g_aggg, TB>>>(dout, 64, b2, y, 128, n);

    // ---- layer 3 (64 -> 64): hs into g_y cols 64..127, result -> d_out ----
    k_gemm64<64><<<g_gemm, TB>>>(y, 128, W3, 64, 0, y + 64, 128, n);
    k_agg<false><<<g_aggg, TB>>>(y + 64, 128, b3, dout, 64, n);
}

// round 4
// speedup vs baseline: 2.5703x; 1.1141x over previous
#include <cuda_runtime.h>
#include <math.h>

#define NMAX   100000
#define EMAX   1600000
#define SCAN_B 512

// Static scratch ~59 MB (unchanged from the passing round-3 footprint).
__device__ float g_y[(size_t)NMAX * 128];   // persistent feature buffer (stride 128)
__device__ float g_dinv[NMAX];
__device__ int   g_deg[NMAX];     // edge-only in-degree
__device__ int   g_rowptr[NMAX];  // exclusive scan of g_deg
__device__ int   g_cursor[NMAX];
__device__ int   g_csr[EMAX];     // src ids grouped by dst
__device__ int   g_bsums[1024];

// ---------------- degree / norm / CSR ----------------
__global__ void k_zero(int n) {
    int i = blockIdx.x * blockDim.x + threadIdx.x;
    if (i < n) { g_deg[i] = 0; g_cursor[i] = 0; }
}

__global__ void k_deg_count(const int* __restrict__ dst, int E) {
    int e = blockIdx.x * blockDim.x + threadIdx.x;
    if (e < E) atomicAdd(&g_deg[dst[e]], 1);
}

__global__ void k_dinv(int n) {
    int i = blockIdx.x * blockDim.x + threadIdx.x;
    if (i < n) g_dinv[i] = rsqrtf((float)(g_deg[i] + 1));  // +1 self loop
}

// exclusive scan of g_deg -> g_rowptr (3-phase)
__global__ void k_scan1(int n) {
    __shared__ int sm[SCAN_B];
    int gid = blockIdx.x * SCAN_B + threadIdx.x;
    int v = (gid < n) ? g_deg[gid] : 0;
    sm[threadIdx.x] = v;
    __syncthreads();
    for (int off = 1; off < SCAN_B; off <<= 1) {
        int t = (threadIdx.x >= off) ? sm[threadIdx.x - off] : 0;
        __syncthreads();
        sm[threadIdx.x] += t;
        __syncthreads();
    }
    if (gid < n) g_rowptr[gid] = sm[threadIdx.x] - v;
    if (threadIdx.x == SCAN_B - 1) g_bsums[blockIdx.x] = sm[SCAN_B - 1];
}

__global__ void k_scan2(int nb) {  // single block, nb <= SCAN_B
    __shared__ int sm[SCAN_B];
    int v = (threadIdx.x < nb) ? g_bsums[threadIdx.x] : 0;
    sm[threadIdx.x] = v;
    __syncthreads();
    for (int off = 1; off < SCAN_B; off <<= 1) {
        int t = (threadIdx.x >= off) ? sm[threadIdx.x - off] : 0;
        __syncthreads();
        sm[threadIdx.x] += t;
        __syncthreads();
    }
    if (threadIdx.x < nb) g_bsums[threadIdx.x] = sm[threadIdx.x];  // inclusive
}

__global__ void k_scan3(int n) {
    int gid = blockIdx.x * SCAN_B + threadIdx.x;
    if (gid >= n || blockIdx.x == 0) return;
    g_rowptr[gid] += g_bsums[blockIdx.x - 1];
}

__global__ void k_place(const int* __restrict__ src, const int* __restrict__ dst, int E) {
    int e = blockIdx.x * blockDim.x + threadIdx.x;
    if (e >= E) return;
    int d = dst[e];
    int pos = g_rowptr[d] + atomicAdd(&g_cursor[d], 1);
    g_csr[pos] = src[e];
}

// ---------------- layer-1 pre-scale: xs[r,c] = x[r,c]*dinv[r], padded stride 16 ----------------
__global__ void k_xscale(const float* __restrict__ x, float* __restrict__ xs, int n) {
    int idx = blockIdx.x * blockDim.x + threadIdx.x;
    if (idx >= n * 16) return;
    int r = idx >> 4, c = idx & 15;
    xs[idx] = (c < 13) ? x[r * 13 + c] * g_dinv[r] : 0.0f;
}

// ---------------- 13(16)-channel CSR aggregation: Xa[d] = dinv[d]*(xs[d]+sum xs[s]) ----------------
__global__ void k_agg13(const float* __restrict__ xs, float* __restrict__ xa, int n) {
    int node = blockIdx.x * (blockDim.x >> 5) + (threadIdx.x >> 5);
    int lane = threadIdx.x & 31;
    if (node >= n) return;

    float acc = (lane < 16) ? xs[node * 16 + lane] : 0.0f;
    int start = g_rowptr[node];
    int end = start + g_deg[node];

    for (int j0 = start; j0 < end; j0 += 32) {
        int idx = 0;
        if (j0 + lane < end) idx = __ldg(&g_csr[j0 + lane]);
        int cnt = min(32, end - j0);
        int t = 0;
        for (; t + 4 <= cnt; t += 4) {
            int s0 = __shfl_sync(0xffffffffu, idx, t + 0);
            int s1 = __shfl_sync(0xffffffffu, idx, t + 1);
            int s2 = __shfl_sync(0xffffffffu, idx, t + 2);
            int s3 = __shfl_sync(0xffffffffu, idx, t + 3);
            float v0 = 0, v1 = 0, v2 = 0, v3 = 0;
            if (lane < 16) {
                v0 = xs[s0 * 16 + lane];
                v1 = xs[s1 * 16 + lane];
                v2 = xs[s2 * 16 + lane];
                v3 = xs[s3 * 16 + lane];
            }
            acc += (v0 + v1) + (v2 + v3);
        }
        for (; t < cnt; ++t) {
            int s = __shfl_sync(0xffffffffu, idx, t);
            if (lane < 16) acc += xs[s * 16 + lane];
        }
    }
    if (lane < 16) xa[node * 16 + lane] = acc * g_dinv[node];
}

// ---------------- layer-1 GEMM: y1 = relu(Xa @ W1 + b1), COUT=128 ----------------
__global__ void k_gemm_l1(const float* __restrict__ xa, const float* __restrict__ W,
                          const float* __restrict__ b, float* __restrict__ y, int n) {
    constexpr int TB = 256, COUT = 128, CIN = 13, RP = TB / COUT, ITER = 16;
    __shared__ float Ws[CIN * COUT];
    __shared__ float xsm[RP][16];

    for (int i = threadIdx.x; i < CIN * COUT; i += TB) Ws[i] = W[i];

    const int c = threadIdx.x % COUT;
    const int rsub = threadIdx.x / COUT;
    const int row0 = blockIdx.x * (RP * ITER);
    const float bc = __ldg(b + c);

#pragma unroll
    for (int it = 0; it < ITER; ++it) {
        __syncthreads();
        for (int i = threadIdx.x; i < RP * 16; i += TB) {
            int rr = row0 + it * RP + i / 16;
            xsm[i / 16][i % 16] = (rr < n) ? xa[rr * 16 + (i % 16)] : 0.0f;
        }
        __syncthreads();
        int r = row0 + it * RP + rsub;
        if (r < n) {
            float acc = bc;
#pragma unroll
            for (int k = 0; k < CIN; ++k)
                acc = fmaf(xsm[rsub][k], Ws[k * COUT + c], acc);
            y[(size_t)r * 128 + c] = fmaxf(acc, 0.0f);
        }
    }
}

// ---------------- GEMM (COUT=64): hs = (x @ W) * dinv ----------------
template <int CIN>
__global__ void k_gemm64(const float* __restrict__ x, int xstride,
                         const float* __restrict__ W,
                         float* __restrict__ hs, int hstride, int n) {
    constexpr int TB = 256, COUT = 64;
    constexpr int RP = TB / COUT, ITER = 8;
    __shared__ float Ws[CIN * COUT];
    __shared__ float xs[RP][CIN];

    for (int i = threadIdx.x; i < CIN * COUT; i += TB) Ws[i] = W[i];

    const int c = threadIdx.x % COUT;
    const int rsub = threadIdx.x / COUT;
    const int row0 = blockIdx.x * (RP * ITER);

#pragma unroll
    for (int it = 0; it < ITER; ++it) {
        __syncthreads();
        for (int i = threadIdx.x; i < RP * CIN; i += TB) {
            int rr = row0 + it * RP + i / CIN;
            xs[i / CIN][i % CIN] = (rr < n) ? x[(size_t)rr * xstride + (i % CIN)] : 0.0f;
        }
        __syncthreads();
        int r = row0 + it * RP + rsub;
        if (r < n) {
            float acc = 0.0f;
#pragma unroll
            for (int k = 0; k < CIN; ++k)
                acc = fmaf(xs[rsub][k], Ws[k * COUT + c], acc);
            hs[(size_t)r * hstride + c] = acc * g_dinv[r];
        }
    }
}

// ---------------- 64-channel CSR aggregation + bias (+relu) ----------------
// y[d] = dinv[d] * (hs[d] + sum_{s in N(d)} hs[s]) + b
template <bool RELU>
__global__ void k_agg(const float* __restrict__ hs, int hstride,
                      const float* __restrict__ b,
                      float* __restrict__ y, int ystride, int n) {
    int node = blockIdx.x * (blockDim.x >> 5) + (threadIdx.x >> 5);
    int lane = threadIdx.x & 31;
    if (node >= n) return;

    float2 acc = *reinterpret_cast<const float2*>(&hs[(size_t)node * hstride + lane * 2]);
    int start = g_rowptr[node];
    int end = start + g_deg[node];

    for (int j0 = start; j0 < end; j0 += 32) {
        int idx = 0;
        if (j0 + lane < end) idx = __ldg(&g_csr[j0 + lane]);
        int cnt = min(32, end - j0);
        int t = 0;
        for (; t + 8 <= cnt; t += 8) {
            float2 v[8];
#pragma unroll
            for (int u = 0; u < 8; ++u) {
                int s = __shfl_sync(0xffffffffu, idx, t + u);
                v[u] = *reinterpret_cast<const float2*>(&hs[(size_t)s * hstride + lane * 2]);
            }
#pragma unroll
            for (int u = 0; u < 8; ++u) { acc.x += v[u].x; acc.y += v[u].y; }
        }
        for (; t < cnt; ++t) {
            int s = __shfl_sync(0xffffffffu, idx, t);
            float2 v = *reinterpret_cast<const float2*>(&hs[(size_t)s * hstride + lane * 2]);
            acc.x += v.x;
            acc.y += v.y;
        }
    }

    float dv = g_dinv[node];
    float2 bb = *reinterpret_cast<const float2*>(&b[lane * 2]);
    float2 o;
    o.x = fmaf(acc.x, dv, bb.x);
    o.y = fmaf(acc.y, dv, bb.y);
    if (RELU) { o.x = fmaxf(o.x, 0.0f); o.y = fmaxf(o.y, 0.0f); }
    *reinterpret_cast<float2*>(&y[(size_t)node * ystride + lane * 2]) = o;
}

// ---------------- launch ----------------
extern "C" void kernel_launch(void* const* d_in, const int* in_sizes, int n_in,
                              void* d_out, int out_size) {
    const float* x  = (const float*)d_in[0];
    const int*   ei = (const int*)d_in[1];
    const float* W1 = (const float*)d_in[2];
    const float* b1 = (const float*)d_in[3];
    const float* W2 = (const float*)d_in[4];
    const float* b2 = (const float*)d_in[5];
    const float* W3 = (const float*)d_in[6];
    const float* b3 = (const float*)d_in[7];
    float* dout = (float*)d_out;  // N x 64 floats — scratch for xs/Xa, then hs, then result

    const int n = in_sizes[0] / 13;
    const int E = in_sizes[1] / 2;
    const int* src = ei;
    const int* dst = ei + E;

    const int TB = 256;
    auto cdiv = [](long long a, long long b) { return (int)((a + b - 1) / b); };
    const int g_gemm = cdiv(n, 32);
    const int g_aggg = cdiv(n, TB / 32);
    const int nb = cdiv(n, SCAN_B);

    float* y = nullptr;
    cudaGetSymbolAddress((void**)&y, g_y);  // stride 128

    // d_out as layer-1 scratch (dead once k_gemm_l1 finishes)
    float* xs = dout;           // N x 16
    float* xa = dout + n * 16;  // N x 16

    // ---- CSR build (once; shared by all layers) ----
    k_zero<<<cdiv(n, TB), TB>>>(n);
    k_deg_count<<<cdiv(E, TB), TB>>>(dst, E);
    k_dinv<<<cdiv(n, TB), TB>>>(n);
    k_scan1<<<nb, SCAN_B>>>(n);
    k_scan2<<<1, SCAN_B>>>(nb);
    k_scan3<<<nb, SCAN_B>>>(n);
    k_place<<<cdiv(E, TB), TB>>>(src, dst, E);

    // ---- layer 1: aggregate-first (13 ch), then 13->128 GEMM w/ fused bias+relu ----
    k_xscale<<<cdiv((long long)n * 16, TB), TB>>>(x, xs, n);
    k_agg13<<<g_aggg, TB>>>(xs, xa, n);
    k_gemm_l1<<<g_gemm, TB>>>(xa, W1, b1, y, n);

    // ---- layer 2 (128 -> 64): hs in d_out, y2 -> g_y cols 0..63 ----
    k_gemm64<128><<<g_gemm, TB>>>(y, 128, W2, dout, 64, n);
    k_agg<true><<<g_aggg, TB>>>(dout, 64, b2, y, 128, n);

    // ---- layer 3 (64 -> 64): hs -> g_y cols 64..127, result -> d_out ----
    k_gemm64<64><<<g_gemm, TB>>>(y, 128, W3, y + 64, 128, n);
    k_agg<false><<<g_aggg, TB>>>(y + 64, 128, b3, dout, 64, n);
}

// round 5
// speedup vs baseline: 3.7606x; 1.4631x over previous
#include <cuda_runtime.h>
#include <cuda_fp16.h>
#include <math.h>

#define NMAX   100000
#define EMAX   1600000
#define SCAN_B 512

// Static scratch ~59 MB.
__device__ float g_y[(size_t)NMAX * 128];   // persistent feature buffer (stride 128)
__device__ float g_dinv[NMAX];
__device__ int   g_deg[NMAX];
__device__ int   g_rowptr[NMAX];
__device__ int   g_cursor[NMAX];
__device__ int   g_csr[EMAX];
__device__ int   g_bsums[1024];

// ---------------- degree / norm / CSR ----------------
__global__ void k_zero(int n) {
    int i = blockIdx.x * blockDim.x + threadIdx.x;
    if (i < n) { g_deg[i] = 0; g_cursor[i] = 0; }
}

__global__ void k_deg_count(const int* __restrict__ dst, int E) {
    int e = blockIdx.x * blockDim.x + threadIdx.x;
    if (e < E) atomicAdd(&g_deg[dst[e]], 1);
}

__global__ void k_dinv(int n) {
    int i = blockIdx.x * blockDim.x + threadIdx.x;
    if (i < n) g_dinv[i] = rsqrtf((float)(g_deg[i] + 1));  // +1 self loop
}

__global__ void k_scan1(int n) {
    __shared__ int sm[SCAN_B];
    int gid = blockIdx.x * SCAN_B + threadIdx.x;
    int v = (gid < n) ? g_deg[gid] : 0;
    sm[threadIdx.x] = v;
    __syncthreads();
    for (int off = 1; off < SCAN_B; off <<= 1) {
        int t = (threadIdx.x >= off) ? sm[threadIdx.x - off] : 0;
        __syncthreads();
        sm[threadIdx.x] += t;
        __syncthreads();
    }
    if (gid < n) g_rowptr[gid] = sm[threadIdx.x] - v;
    if (threadIdx.x == SCAN_B - 1) g_bsums[blockIdx.x] = sm[SCAN_B - 1];
}

__global__ void k_scan2(int nb) {
    __shared__ int sm[SCAN_B];
    int v = (threadIdx.x < nb) ? g_bsums[threadIdx.x] : 0;
    sm[threadIdx.x] = v;
    __syncthreads();
    for (int off = 1; off < SCAN_B; off <<= 1) {
        int t = (threadIdx.x >= off) ? sm[threadIdx.x - off] : 0;
        __syncthreads();
        sm[threadIdx.x] += t;
        __syncthreads();
    }
    if (threadIdx.x < nb) g_bsums[threadIdx.x] = sm[threadIdx.x];
}

__global__ void k_scan3(int n) {
    int gid = blockIdx.x * SCAN_B + threadIdx.x;
    if (gid >= n || blockIdx.x == 0) return;
    g_rowptr[gid] += g_bsums[blockIdx.x - 1];
}

__global__ void k_place(const int* __restrict__ src, const int* __restrict__ dst, int E) {
    int e = blockIdx.x * blockDim.x + threadIdx.x;
    if (e >= E) return;
    int d = dst[e];
    int pos = g_rowptr[d] + atomicAdd(&g_cursor[d], 1);
    g_csr[pos] = src[e];
}

// ---------------- layer-1 pre-scale ----------------
__global__ void k_xscale(const float* __restrict__ x, float* __restrict__ xs, int n) {
    int idx = blockIdx.x * blockDim.x + threadIdx.x;
    if (idx >= n * 16) return;
    int r = idx >> 4, c = idx & 15;
    xs[idx] = (c < 13) ? x[r * 13 + c] * g_dinv[r] : 0.0f;
}

// ---------------- 13(16)-ch aggregation, 2 neighbors/step ----------------
__global__ void k_agg13(const float* __restrict__ xs, float* __restrict__ xa, int n) {
    int node = blockIdx.x * (blockDim.x >> 5) + (threadIdx.x >> 5);
    int lane = threadIdx.x & 31;
    if (node >= n) return;
    const int hf = lane >> 4;  // half-warp id: neighbor A or B
    const int c = lane & 15;

    float acc = (hf == 0) ? xs[node * 16 + c] : 0.0f;  // self term once
    int start = g_rowptr[node];
    int end = start + g_deg[node];

    for (int j0 = start; j0 < end; j0 += 32) {
        int idx = 0;
        if (j0 + lane < end) idx = __ldg(&g_csr[j0 + lane]);
        int cnt = min(32, end - j0);
        int t = 0;
        for (; t + 8 <= cnt; t += 8) {
            float v[4];
#pragma unroll
            for (int u = 0; u < 4; ++u) {
                int s = __shfl_sync(0xffffffffu, idx, t + 2 * u + hf);
                v[u] = xs[s * 16 + c];
            }
            acc += (v[0] + v[1]) + (v[2] + v[3]);
        }
        for (; t + 2 <= cnt; t += 2) {
            int s = __shfl_sync(0xffffffffu, idx, t + hf);
            acc += xs[s * 16 + c];
        }
        if (t < cnt) {
            int s = __shfl_sync(0xffffffffu, idx, t);
            if (hf == 0) acc += xs[s * 16 + c];
        }
    }
    acc += __shfl_down_sync(0xffffffffu, acc, 16);
    if (hf == 0) xa[node * 16 + c] = acc * g_dinv[node];
}

// ---------------- register-tiled GEMM ----------------
// L1OUT: yout = relu(x@W + bias), fp32.  else: hout = (x@W)*dinv, fp16.
// Thread tile: 2 rows x CPT cols. Block tile: 32 rows x COUT cols, ITER tiles.
template <int CIN, int COUT, int ITER, bool L1OUT>
__global__ void k_gemm_rt(const float* __restrict__ x, int xstride,
                          const float* __restrict__ W,
                          const float* __restrict__ bias,
                          float* __restrict__ yout, int ystride,
                          __half* __restrict__ hout, int hstride, int n) {
    constexpr int TB = 256;
    constexpr int ROWS = 32;
    constexpr int CPT = COUT / 16;            // 4 or 8
    constexpr int KCH = (CIN > 64) ? 64 : CIN;
    constexpr int NCH = CIN / KCH;
    constexpr int SXS = (KCH == 13) ? 20 : KCH + 4;  // bank-spread pad

    __shared__ float Ws[CIN * COUT];
    __shared__ float xs[ROWS * SXS];

    {  // W load (float4, coalesced)
        const float4* Wv = (const float4*)W;
        for (int i = threadIdx.x; i < CIN * COUT / 4; i += TB)
            ((float4*)Ws)[i] = Wv[i];
    }

    const int cg = threadIdx.x & 15;  // col group -> cols [cg*CPT, cg*CPT+CPT)
    const int rg = threadIdx.x >> 4;  // rows {2rg, 2rg+1}
    float bb[CPT];
    if (L1OUT) {
#pragma unroll
        for (int j = 0; j < CPT; ++j) bb[j] = __ldg(bias + cg * CPT + j);
    }

    for (int it = 0; it < ITER; ++it) {
        const int rowbase = (blockIdx.x * ITER + it) * ROWS;
        if (rowbase >= n) break;
        float acc[2][CPT];
#pragma unroll
        for (int j = 0; j < CPT; ++j) {
            acc[0][j] = L1OUT ? bb[j] : 0.0f;
            acc[1][j] = L1OUT ? bb[j] : 0.0f;
        }

        for (int ch = 0; ch < NCH; ++ch) {
            __syncthreads();
            if (KCH % 4 == 0) {
                constexpr int K4 = KCH / 4;
                for (int i = threadIdx.x; i < ROWS * K4; i += TB) {
                    int row = i / K4, c4 = i % K4;
                    int rr = rowbase + row;
                    float4 v = make_float4(0, 0, 0, 0);
                    if (rr < n)
                        v = *(const float4*)(x + (size_t)rr * xstride + ch * KCH + c4 * 4);
                    *(float4*)&xs[row * SXS + c4 * 4] = v;
                }
            } else {
                for (int i = threadIdx.x; i < ROWS * KCH; i += TB) {
                    int row = i / KCH, c = i % KCH;
                    int rr = rowbase + row;
                    xs[row * SXS + c] =
                        (rr < n) ? x[(size_t)rr * xstride + ch * KCH + c] : 0.0f;
                }
            }
            __syncthreads();
            const float* wbase = Ws + ch * KCH * COUT + cg * CPT;
            const float* x0 = xs + (2 * rg) * SXS;
            const float* x1 = x0 + SXS;
#pragma unroll 4
            for (int k = 0; k < KCH; ++k) {
                float a0 = x0[k], a1 = x1[k];
                const float4* wr = (const float4*)(wbase + k * COUT);
#pragma unroll
                for (int j4 = 0; j4 < CPT / 4; ++j4) {
                    float4 w = wr[j4];
                    acc[0][j4 * 4 + 0] = fmaf(a0, w.x, acc[0][j4 * 4 + 0]);
                    acc[0][j4 * 4 + 1] = fmaf(a0, w.y, acc[0][j4 * 4 + 1]);
                    acc[0][j4 * 4 + 2] = fmaf(a0, w.z, acc[0][j4 * 4 + 2]);
                    acc[0][j4 * 4 + 3] = fmaf(a0, w.w, acc[0][j4 * 4 + 3]);
                    acc[1][j4 * 4 + 0] = fmaf(a1, w.x, acc[1][j4 * 4 + 0]);
                    acc[1][j4 * 4 + 1] = fmaf(a1, w.y, acc[1][j4 * 4 + 1]);
                    acc[1][j4 * 4 + 2] = fmaf(a1, w.z, acc[1][j4 * 4 + 2]);
                    acc[1][j4 * 4 + 3] = fmaf(a1, w.w, acc[1][j4 * 4 + 3]);
                }
            }
        }

#pragma unroll
        for (int rr = 0; rr < 2; ++rr) {
            int r = rowbase + 2 * rg + rr;
            if (r >= n) continue;
            if (L1OUT) {
                float* yp = yout + (size_t)r * ystride + cg * CPT;
#pragma unroll
                for (int j4 = 0; j4 < CPT / 4; ++j4) {
                    float4 o;
                    o.x = fmaxf(acc[rr][j4 * 4 + 0], 0.0f);
                    o.y = fmaxf(acc[rr][j4 * 4 + 1], 0.0f);
                    o.z = fmaxf(acc[rr][j4 * 4 + 2], 0.0f);
                    o.w = fmaxf(acc[rr][j4 * 4 + 3], 0.0f);
                    *(float4*)(yp + j4 * 4) = o;
                }
            } else {
                float dv = g_dinv[r];
                __half2* hp = (__half2*)(hout + (size_t)r * hstride + cg * CPT);
#pragma unroll
                for (int j2 = 0; j2 < CPT / 2; ++j2)
                    hp[j2] = __floats2half2_rn(acc[rr][j2 * 2] * dv,
                                               acc[rr][j2 * 2 + 1] * dv);
            }
        }
    }
}

// ---------------- 64-ch aggregation over fp16 hs + bias (+relu) ----------------
// y[d] = dinv[d] * (hs[d] + sum_{s in N(d)} hs[s]) + b      (fp32 accumulate)
template <bool RELU>
__global__ void k_aggh(const __half2* __restrict__ hs, int sH2,
                       const float* __restrict__ b,
                       float* __restrict__ y, int ystride, int n) {
    int node = blockIdx.x * (blockDim.x >> 5) + (threadIdx.x >> 5);
    int lane = threadIdx.x & 31;
    if (node >= n) return;

    float2 f = __half22float2(hs[(size_t)node * sH2 + lane]);
    float ax = f.x, ay = f.y;
    int start = g_rowptr[node];
    int end = start + g_deg[node];

    for (int j0 = start; j0 < end; j0 += 32) {
        int idx = 0;
        if (j0 + lane < end) idx = __ldg(&g_csr[j0 + lane]);
        int cnt = min(32, end - j0);
        int t = 0;
        for (; t + 8 <= cnt; t += 8) {
            float2 v[8];
#pragma unroll
            for (int u = 0; u < 8; ++u) {
                int s = __shfl_sync(0xffffffffu, idx, t + u);
                v[u] = __half22float2(__ldg(&hs[(size_t)s * sH2 + lane]));
            }
#pragma unroll
            for (int u = 0; u < 8; ++u) { ax += v[u].x; ay += v[u].y; }
        }
        for (; t < cnt; ++t) {
            int s = __shfl_sync(0xffffffffu, idx, t);
            float2 v = __half22float2(__ldg(&hs[(size_t)s * sH2 + lane]));
            ax += v.x; ay += v.y;
        }
    }

    float dv = g_dinv[node];
    float2 bb = *(const float2*)(b + lane * 2);
    float ox = fmaf(ax, dv, bb.x);
    float oy = fmaf(ay, dv, bb.y);
    if (RELU) { ox = fmaxf(ox, 0.0f); oy = fmaxf(oy, 0.0f); }
    *(float2*)&y[(size_t)node * ystride + lane * 2] = make_float2(ox, oy);
}

// ---------------- launch ----------------
extern "C" void kernel_launch(void* const* d_in, const int* in_sizes, int n_in,
                              void* d_out, int out_size) {
    const float* x  = (const float*)d_in[0];
    const int*   ei = (const int*)d_in[1];
    const float* W1 = (const float*)d_in[2];
    const float* b1 = (const float*)d_in[3];
    const float* W2 = (const float*)d_in[4];
    const float* b2 = (const float*)d_in[5];
    const float* W3 = (const float*)d_in[6];
    const float* b3 = (const float*)d_in[7];
    float* dout = (float*)d_out;  // scratch: xs/xa, then hs2 (fp16), finally result

    const int n = in_sizes[0] / 13;
    const int E = in_sizes[1] / 2;
    const int* src = ei;
    const int* dst = ei + E;

    const int TB = 256;
    auto cdiv = [](long long a, long long b) { return (int)((a + b - 1) / b); };
    const int g_aggg = cdiv(n, TB / 32);
    const int g_rt = cdiv(n, 32 * 8);
    const int nb = cdiv(n, SCAN_B);

    float* y = nullptr;
    cudaGetSymbolAddress((void**)&y, g_y);  // stride 128

    float* xs = dout;            // N x 16 fp32
    float* xa = dout + n * 16;   // N x 16 fp32
    __half* hs2 = (__half*)dout;          // N x 64 fp16 (rows = 128 B)
    __half* hs3 = (__half*)(y + 64);      // in g_y cols 64..127, row stride 256 halves

    // ---- CSR build (once; shared by all layers) ----
    k_zero<<<cdiv(n, TB), TB>>>(n);
    k_deg_count<<<cdiv(E, TB), TB>>>(dst, E);
    k_dinv<<<cdiv(n, TB), TB>>>(n);
    k_scan1<<<nb, SCAN_B>>>(n);
    k_scan2<<<1, SCAN_B>>>(nb);
    k_scan3<<<nb, SCAN_B>>>(n);
    k_place<<<cdiv(E, TB), TB>>>(src, dst, E);

    // ---- layer 1: aggregate-first (13 ch), then 13->128 GEMM (bias+relu fused) ----
    k_xscale<<<cdiv((long long)n * 16, TB), TB>>>(x, xs, n);
    k_agg13<<<g_aggg, TB>>>(xs, xa, n);
    k_gemm_rt<13, 128, 8, true><<<g_rt, TB>>>(xa, 16, W1, b1, y, 128, nullptr, 0, n);

    // ---- layer 2 (128 -> 64): hs2 fp16 in d_out, y2 -> g_y cols 0..63 ----
    k_gemm_rt<128, 64, 8, false><<<g_rt, TB>>>(y, 128, W2, nullptr, nullptr, 0, hs2, 64, n);
    k_aggh<true><<<g_aggg, TB>>>((const __half2*)hs2, 32, b2, y, 128, n);

    // ---- layer 3 (64 -> 64): hs3 fp16 in g_y cols 64..127, result -> d_out ----
    k_gemm_rt<64, 64, 8, false><<<g_rt, TB>>>(y, 128, W3, nullptr, nullptr, 0, hs3, 256, n);
    k_aggh<false><<<g_aggg, TB>>>((const __half2*)hs3, 128, b3, dout, 64, n);
}

// round 6
// speedup vs baseline: 3.8508x; 1.0240x over previous
#include <cuda_runtime.h>
#include <cuda_fp16.h>
#include <math.h>

#define NMAX   100000
#define EMAX   1600000
#define SCAN_B 512

// Static scratch ~59 MB.
__device__ float g_y[(size_t)NMAX * 128];   // persistent feature buffer (stride 128 f32)
__device__ float g_dinv[NMAX];
__device__ int   g_deg[NMAX];
__device__ int   g_rowptr[NMAX];
__device__ int   g_cursor[NMAX];
__device__ int   g_csr[EMAX];
__device__ int   g_bsums[1024];

// ---------------- degree / norm / CSR ----------------
__global__ void k_zero(int n) {
    int i = blockIdx.x * blockDim.x + threadIdx.x;
    if (i < n) { g_deg[i] = 0; g_cursor[i] = 0; }
}

__global__ void k_deg_count(const int* __restrict__ dst, int E) {
    int e = blockIdx.x * blockDim.x + threadIdx.x;
    if (e < E) atomicAdd(&g_deg[dst[e]], 1);
}

__global__ void k_dinv(int n) {
    int i = blockIdx.x * blockDim.x + threadIdx.x;
    if (i < n) g_dinv[i] = rsqrtf((float)(g_deg[i] + 1));  // +1 self loop
}

// warp-shuffle block scan
__global__ void k_scan1(int n) {
    __shared__ int wsum[SCAN_B / 32];
    int gid = blockIdx.x * SCAN_B + threadIdx.x;
    int v = (gid < n) ? g_deg[gid] : 0;
    int lane = threadIdx.x & 31, wid = threadIdx.x >> 5;
    int incl = v;
#pragma unroll
    for (int o = 1; o < 32; o <<= 1) {
        int t = __shfl_up_sync(0xffffffffu, incl, o);
        if (lane >= o) incl += t;
    }
    if (lane == 31) wsum[wid] = incl;
    __syncthreads();
    if (wid == 0) {
        int s = (lane < SCAN_B / 32) ? wsum[lane] : 0;
#pragma unroll
        for (int o = 1; o < SCAN_B / 32; o <<= 1) {
            int t = __shfl_up_sync(0xffffffffu, s, o);
            if (lane >= o) s += t;
        }
        if (lane < SCAN_B / 32) wsum[lane] = s;
    }
    __syncthreads();
    int off = wid ? wsum[wid - 1] : 0;
    if (gid < n) g_rowptr[gid] = off + incl - v;  // exclusive
    if (threadIdx.x == SCAN_B - 1) g_bsums[blockIdx.x] = off + incl;
}

__global__ void k_scan2(int nb) {  // single block, nb <= SCAN_B
    __shared__ int sm[SCAN_B];
    int v = (threadIdx.x < nb) ? g_bsums[threadIdx.x] : 0;
    sm[threadIdx.x] = v;
    __syncthreads();
    for (int off = 1; off < SCAN_B; off <<= 1) {
        int t = (threadIdx.x >= off) ? sm[threadIdx.x - off] : 0;
        __syncthreads();
        sm[threadIdx.x] += t;
        __syncthreads();
    }
    if (threadIdx.x < nb) g_bsums[threadIdx.x] = sm[threadIdx.x];  // inclusive
}

__global__ void k_scan3(int n) {
    int gid = blockIdx.x * SCAN_B + threadIdx.x;
    if (gid >= n || blockIdx.x == 0) return;
    g_rowptr[gid] += g_bsums[blockIdx.x - 1];
}

__global__ void k_place(const int* __restrict__ src, const int* __restrict__ dst, int E) {
    int e = blockIdx.x * blockDim.x + threadIdx.x;
    if (e >= E) return;
    int d = __ldg(dst + e);
    int pos = g_rowptr[d] + atomicAdd(&g_cursor[d], 1);
    g_csr[pos] = __ldg(src + e);
}

// ---------------- layer-1 pre-scale: xs_h2[r][p] = half2(x[r,2p]*dinv, x[r,2p+1]*dinv) ----------------
__global__ void k_xscale(const float* __restrict__ x, __half2* __restrict__ xs, int n) {
    int idx = blockIdx.x * blockDim.x + threadIdx.x;
    if (idx >= n * 8) return;
    int r = idx >> 3, p = idx & 7;
    float dv = g_dinv[r];
    int c0 = 2 * p, c1 = 2 * p + 1;
    float v0 = (c0 < 13) ? x[r * 13 + c0] * dv : 0.0f;
    float v1 = (c1 < 13) ? x[r * 13 + c1] * dv : 0.0f;
    xs[idx] = __floats2half2_rn(v0, v1);
}

// ---------------- 13(16)-ch aggregation, fp16 rows, 4 neighbors/step ----------------
// quarter-warp qw (0..3) owns neighbor t+qw; lane cl (0..7) owns half2 channel pair cl.
__global__ void k_agg13(const __half2* __restrict__ xs, float* __restrict__ xa, int n) {
    int node = blockIdx.x * (blockDim.x >> 5) + (threadIdx.x >> 5);
    int lane = threadIdx.x & 31;
    if (node >= n) return;
    const int qw = lane >> 3;
    const int cl = lane & 7;

    float ax = 0.0f, ay = 0.0f;
    if (qw == 0) {  // self term once
        float2 f = __half22float2(xs[node * 8 + cl]);
        ax = f.x; ay = f.y;
    }
    int start = g_rowptr[node];
    int end = start + g_deg[node];

    for (int j0 = start; j0 < end; j0 += 32) {
        int idx = 0;
        if (j0 + lane < end) idx = __ldg(&g_csr[j0 + lane]);
        int cnt = min(32, end - j0);
        int t = 0;
        for (; t + 8 <= cnt; t += 8) {
            int s0 = __shfl_sync(0xffffffffu, idx, t + qw);
            int s1 = __shfl_sync(0xffffffffu, idx, t + 4 + qw);
            float2 v0 = __half22float2(__ldg(&xs[s0 * 8 + cl]));
            float2 v1 = __half22float2(__ldg(&xs[s1 * 8 + cl]));
            ax += v0.x + v1.x;
            ay += v0.y + v1.y;
        }
        for (; t + 4 <= cnt; t += 4) {
            int s = __shfl_sync(0xffffffffu, idx, t + qw);
            float2 v = __half22float2(__ldg(&xs[s * 8 + cl]));
            ax += v.x; ay += v.y;
        }
        int rem = cnt - t;
        if (rem > 0) {
            int s = __shfl_sync(0xffffffffu, idx, t + (qw < rem ? qw : 0));
            if (qw < rem) {
                float2 v = __half22float2(__ldg(&xs[s * 8 + cl]));
                ax += v.x; ay += v.y;
            }
        }
    }
    // reduce across the 4 quarter-warps
    ax += __shfl_down_sync(0xffffffffu, ax, 16);
    ay += __shfl_down_sync(0xffffffffu, ay, 16);
    ax += __shfl_down_sync(0xffffffffu, ax, 8);
    ay += __shfl_down_sync(0xffffffffu, ay, 8);
    if (lane < 8) {
        float dv = g_dinv[node];
        *(float2*)&xa[node * 16 + cl * 2] = make_float2(ax * dv, ay * dv);
    }
}

// ---------------- register-tiled GEMM ----------------
// IN_HALF: input rows are fp16 (xstride in halves). Output is always fp16:
//   L1OUT: out = relu(x@W + bias)    else: out = (x@W) * dinv[r]
// Thread tile: 2 rows x CPT cols. Block tile: 32 rows x COUT, ITER tiles per block.
template <int CIN, int COUT, int ITER, bool IN_HALF, bool L1OUT>
__global__ void k_gemm_rt(const void* __restrict__ xin, int xstride,
                          const float* __restrict__ W,
                          const float* __restrict__ bias,
                          __half* __restrict__ hout, int hstride, int n) {
    constexpr int TB = 256;
    constexpr int ROWS = 32;
    constexpr int CPT = COUT / 16;            // 4 or 8
    constexpr int KCH = (CIN > 64) ? 64 : CIN;
    constexpr int NCH = CIN / KCH;
    constexpr int SXS = (KCH == 13) ? 20 : KCH + 4;

    __shared__ float Ws[CIN * COUT];
    __shared__ float xs[ROWS * SXS];

    {
        const float4* Wv = (const float4*)W;
        for (int i = threadIdx.x; i < CIN * COUT / 4; i += TB)
            ((float4*)Ws)[i] = Wv[i];
    }

    const int cg = threadIdx.x & 15;
    const int rg = threadIdx.x >> 4;
    float bb[CPT];
    if (L1OUT) {
#pragma unroll
        for (int j = 0; j < CPT; ++j) bb[j] = __ldg(bias + cg * CPT + j);
    }

    for (int it = 0; it < ITER; ++it) {
        const int rowbase = (blockIdx.x * ITER + it) * ROWS;
        if (rowbase >= n) break;
        float acc[2][CPT];
#pragma unroll
        for (int j = 0; j < CPT; ++j) {
            acc[0][j] = L1OUT ? bb[j] : 0.0f;
            acc[1][j] = L1OUT ? bb[j] : 0.0f;
        }

        for (int ch = 0; ch < NCH; ++ch) {
            __syncthreads();
            if (IN_HALF) {
                const __half2* xh = (const __half2*)xin;
                constexpr int K2 = KCH / 2;
                for (int i = threadIdx.x; i < ROWS * K2; i += TB) {
                    int row = i / K2, c2 = i % K2;
                    int rr = rowbase + row;
                    float2 v = make_float2(0.0f, 0.0f);
                    if (rr < n)
                        v = __half22float2(
                            __ldg(&xh[(size_t)rr * (xstride / 2) + (ch * KCH) / 2 + c2]));
                    *(float2*)&xs[row * SXS + c2 * 2] = v;
                }
            } else if (KCH % 4 == 0) {
                const float* xf = (const float*)xin;
                constexpr int K4 = KCH / 4;
                for (int i = threadIdx.x; i < ROWS * K4; i += TB) {
                    int row = i / K4, c4 = i % K4;
                    int rr = rowbase + row;
                    float4 v = make_float4(0, 0, 0, 0);
                    if (rr < n)
                        v = *(const float4*)(xf + (size_t)rr * xstride + ch * KCH + c4 * 4);
                    *(float4*)&xs[row * SXS + c4 * 4] = v;
                }
            } else {
                const float* xf = (const float*)xin;
                for (int i = threadIdx.x; i < ROWS * KCH; i += TB) {
                    int row = i / KCH, c = i % KCH;
                    int rr = rowbase + row;
                    xs[row * SXS + c] =
                        (rr < n) ? xf[(size_t)rr * xstride + ch * KCH + c] : 0.0f;
                }
            }
            __syncthreads();
            const float* wbase = Ws + ch * KCH * COUT + cg * CPT;
            const float* x0 = xs + (2 * rg) * SXS;
            const float* x1 = x0 + SXS;
#pragma unroll 4
            for (int k = 0; k < KCH; ++k) {
                float a0 = x0[k], a1 = x1[k];
                const float4* wr = (const float4*)(wbase + k * COUT);
#pragma unroll
                for (int j4 = 0; j4 < CPT / 4; ++j4) {
                    float4 w = wr[j4];
                    acc[0][j4 * 4 + 0] = fmaf(a0, w.x, acc[0][j4 * 4 + 0]);
                    acc[0][j4 * 4 + 1] = fmaf(a0, w.y, acc[0][j4 * 4 + 1]);
                    acc[0][j4 * 4 + 2] = fmaf(a0, w.z, acc[0][j4 * 4 + 2]);
                    acc[0][j4 * 4 + 3] = fmaf(a0, w.w, acc[0][j4 * 4 + 3]);
                    acc[1][j4 * 4 + 0] = fmaf(a1, w.x, acc[1][j4 * 4 + 0]);
                    acc[1][j4 * 4 + 1] = fmaf(a1, w.y, acc[1][j4 * 4 + 1]);
                    acc[1][j4 * 4 + 2] = fmaf(a1, w.z, acc[1][j4 * 4 + 2]);
                    acc[1][j4 * 4 + 3] = fmaf(a1, w.w, acc[1][j4 * 4 + 3]);
                }
            }
        }

#pragma unroll
        for (int rr = 0; rr < 2; ++rr) {
            int r = rowbase + 2 * rg + rr;
            if (r >= n) continue;
            __half2* hp = (__half2*)(hout + (size_t)r * hstride + cg * CPT);
            if (L1OUT) {
#pragma unroll
                for (int j2 = 0; j2 < CPT / 2; ++j2)
                    hp[j2] = __floats2half2_rn(fmaxf(acc[rr][j2 * 2], 0.0f),
                                               fmaxf(acc[rr][j2 * 2 + 1], 0.0f));
            } else {
                float dv = g_dinv[r];
#pragma unroll
                for (int j2 = 0; j2 < CPT / 2; ++j2)
                    hp[j2] = __floats2half2_rn(acc[rr][j2 * 2] * dv,
                                               acc[rr][j2 * 2 + 1] * dv);
            }
        }
    }
}

// ---------------- 64-ch aggregation over fp16 hs + bias (+relu) ----------------
// OUT_HALF: y is fp16 (feeds next GEMM). else fp32 (final output).
template <bool RELU, bool OUT_HALF>
__global__ void k_aggh(const __half2* __restrict__ hs, int sH2,
                       const float* __restrict__ b,
                       void* __restrict__ yout, int ystride, int n) {
    int node = blockIdx.x * (blockDim.x >> 5) + (threadIdx.x >> 5);
    int lane = threadIdx.x & 31;
    if (node >= n) return;

    float2 f = __half22float2(hs[(size_t)node * sH2 + lane]);
    float ax = f.x, ay = f.y;
    int start = g_rowptr[node];
    int end = start + g_deg[node];

    for (int j0 = start; j0 < end; j0 += 32) {
        int idx = 0;
        if (j0 + lane < end) idx = __ldg(&g_csr[j0 + lane]);
        int cnt = min(32, end - j0);
        int t = 0;
        for (; t + 8 <= cnt; t += 8) {
            float2 v[8];
#pragma unroll
            for (int u = 0; u < 8; ++u) {
                int s = __shfl_sync(0xffffffffu, idx, t + u);
                v[u] = __half22float2(__ldg(&hs[(size_t)s * sH2 + lane]));
            }
#pragma unroll
            for (int u = 0; u < 8; ++u) { ax += v[u].x; ay += v[u].y; }
        }
        for (; t < cnt; ++t) {
            int s = __shfl_sync(0xffffffffu, idx, t);
            float2 v = __half22float2(__ldg(&hs[(size_t)s * sH2 + lane]));
            ax += v.x; ay += v.y;
        }
    }

    float dv = g_dinv[node];
    float2 bb = *(const float2*)(b + lane * 2);
    float ox = fmaf(ax, dv, bb.x);
    float oy = fmaf(ay, dv, bb.y);
    if (RELU) { ox = fmaxf(ox, 0.0f); oy = fmaxf(oy, 0.0f); }
    if (OUT_HALF) {
        ((__half2*)yout)[(size_t)node * (ystride / 2) + lane] = __floats2half2_rn(ox, oy);
    } else {
        *(float2*)&((float*)yout)[(size_t)node * ystride + lane * 2] = make_float2(ox, oy);
    }
}

// ---------------- launch ----------------
extern "C" void kernel_launch(void* const* d_in, const int* in_sizes, int n_in,
                              void* d_out, int out_size) {
    const float* x  = (const float*)d_in[0];
    const int*   ei = (const int*)d_in[1];
    const float* W1 = (const float*)d_in[2];
    const float* b1 = (const float*)d_in[3];
    const float* W2 = (const float*)d_in[4];
    const float* b2 = (const float*)d_in[5];
    const float* W3 = (const float*)d_in[6];
    const float* b3 = (const float*)d_in[7];
    float* dout = (float*)d_out;  // scratch, finally the fp32 result

    const int n = in_sizes[0] / 13;
    const int E = in_sizes[1] / 2;
    const int* src = ei;
    const int* dst = ei + E;

    const int TB = 256;
    auto cdiv = [](long long a, long long b) { return (int)((a + b - 1) / b); };
    const int g_aggg = cdiv(n, TB / 32);
    const int g_rt = cdiv(n, 32 * 8);
    const int nb = cdiv(n, SCAN_B);

    float* y = nullptr;
    cudaGetSymbolAddress((void**)&y, g_y);

    // Buffer plan (all dead-before-overwrite, sequential stream):
    __half2* xs_h2 = (__half2*)dout;               // N x 8 half2  (layer-1 input, scaled)
    float*   xa    = dout + (size_t)n * 8;         // N x 16 fp32  (aggregated layer-1 input)
    __half*  y1h   = (__half*)y;                   // N x 128 fp16 (relu output layer 1)
    __half*  hs2   = (__half*)dout;                // N x 64 fp16  (overwrites xs/xa region)
    __half*  y2h   = (__half*)(y + (size_t)NMAX * 64);  // N x 64 fp16 (layer-2 output)
    __half*  hs3   = (__half*)y;                   // N x 64 fp16  (overwrites dead y1h)

    // ---- CSR build (once; shared by all layers) ----
    k_zero<<<cdiv(n, TB), TB>>>(n);
    k_deg_count<<<cdiv(E, TB), TB>>>(dst, E);
    k_dinv<<<cdiv(n, TB), TB>>>(n);
    k_scan1<<<nb, SCAN_B>>>(n);
    k_scan2<<<1, SCAN_B>>>(nb);
    k_scan3<<<nb, SCAN_B>>>(n);
    k_place<<<cdiv(E, TB), TB>>>(src, dst, E);

    // ---- layer 1: aggregate-first (13 ch fp16), then 13->128 GEMM (bias+relu fused) ----
    k_xscale<<<cdiv((long long)n * 8, TB), TB>>>(x, xs_h2, n);
    k_agg13<<<g_aggg, TB>>>(xs_h2, xa, n);
    k_gemm_rt<13, 128, 8, false, true><<<g_rt, TB>>>(xa, 16, W1, b1, y1h, 128, n);

    // ---- layer 2 (128 -> 64): hs2 fp16, y2 fp16 ----
    k_gemm_rt<128, 64, 8, true, false><<<g_rt, TB>>>(y1h, 128, W2, nullptr, hs2, 64, n);
    k_aggh<true, true><<<g_aggg, TB>>>((const __half2*)hs2, 32, b2, y2h, 64, n);

    // ---- layer 3 (64 -> 64): hs3 fp16, final fp32 -> d_out ----
    k_gemm_rt<64, 64, 8, true, false><<<g_rt, TB>>>(y2h, 64, W3, nullptr, hs3, 64, n);
    k_aggh<false, false><<<g_aggg, TB>>>((const __half2*)hs3, 32, b3, dout, 64, n);
}